// round 4
// baseline (speedup 1.0000x reference)
#include <cuda_runtime.h>
#include <cuda_bf16.h>
#include <cuda_fp8.h>
#include <cstdint>

#define M_DIM 4096
#define H_DIM 4096
#define I_DIM 14336
#define KB_H (H_DIM/128)
#define KB_I (I_DIM/128)

// ---- static scratch (fp8 storage everywhere) ----
__device__ int g_fmt;
__device__ uint8_t g_wg[(size_t)I_DIM*H_DIM];
__device__ uint8_t g_wu[(size_t)I_DIM*H_DIM];
__device__ uint8_t g_wd[(size_t)H_DIM*I_DIM];
__device__ uint8_t g_xq[(size_t)M_DIM*H_DIM];
__device__ float   g_xs[(size_t)M_DIM*KB_H];
__device__ float   g_gate[(size_t)M_DIM*I_DIM];
__device__ float   g_up[(size_t)M_DIM*I_DIM];
__device__ uint8_t g_hq[(size_t)M_DIM*I_DIM];
__device__ float   g_hs[(size_t)M_DIM*KB_I];

// ---- scalar helpers ----
__device__ __forceinline__ float fp8_to_f32(unsigned char b){
    __half_raw hr = __nv_cvt_fp8_to_halfraw((__nv_fp8_storage_t)b, __NV_E4M3);
    return __half2float(*(__half*)&hr);
}
__device__ __forceinline__ bool fp8_rt(float v){
    if(!isfinite(v) || fabsf(v) > 448.0f) return false;
    __nv_fp8_storage_t b = __nv_cvt_float_to_fp8(v, __NV_SATFINITE, __NV_E4M3);
    return fp8_to_f32((unsigned char)b) == v;
}
__device__ __forceinline__ uint8_t fq8(float v, float s){
    return (uint8_t)__nv_cvt_float_to_fp8(__fdiv_rn(v, s), __NV_SATFINITE, __NV_E4M3);
}
__device__ __forceinline__ float exp_precise(float x){
    float n = rintf(x * 1.4426950408889634f);
    float r = fmaf(n, -0.693359375f, x);
    r = fmaf(n, 2.12194440e-4f, r);
    float p = 1.9841269841e-4f;
    p = fmaf(p, r, 1.3888888888e-3f);
    p = fmaf(p, r, 8.3333333333e-3f);
    p = fmaf(p, r, 4.1666666667e-2f);
    p = fmaf(p, r, 1.6666666667e-1f);
    p = fmaf(p, r, 0.5f);
    p = fmaf(p, r, 1.0f);
    p = fmaf(p, r, 1.0f);
    return ldexpf(p, (int)n);
}
__device__ __forceinline__ float sigmoid_precise(float x){
    float ax = fminf(fabsf(x), 87.0f);
    float e = exp_precise(-ax);
    float den = 1.0f + e;
    return (x >= 0.0f) ? __fdiv_rn(1.0f, den) : __fdiv_rn(e, den);
}
__device__ __forceinline__ void cpasync16(void* s, const void* g){
    unsigned sa = (unsigned)__cvta_generic_to_shared(s);
    asm volatile("cp.async.cg.shared.global [%0], [%1], 16;\n" :: "r"(sa), "l"(g));
}
// FP8 e4m3 MMA, m16n8k32, fp32 accumulate
__device__ __forceinline__ void mma8(float* c, const unsigned* a, const unsigned* b){
    asm volatile("mma.sync.aligned.m16n8k32.row.col.f32.e4m3.e4m3.f32 "
        "{%0,%1,%2,%3}, {%4,%5,%6,%7}, {%8,%9}, {%0,%1,%2,%3};\n"
        : "+f"(c[0]), "+f"(c[1]), "+f"(c[2]), "+f"(c[3])
        : "r"(a[0]), "r"(a[1]), "r"(a[2]), "r"(a[3]), "r"(b[0]), "r"(b[1]));
}

// ---- format detection ----
__global__ void k_detect(const void* __restrict__ w){
    int tid = threadIdx.x;
    int ok32 = 1, ok16 = 1;
    for(int i = tid; i < 2048; i += blockDim.x){
        ok32 = ok32 && fp8_rt(((const float*)w)[i]);
        ok16 = ok16 && fp8_rt(__bfloat162float(((const __nv_bfloat16*)w)[i]));
    }
    int a32 = __syncthreads_and(ok32);
    int a16 = __syncthreads_and(ok16);
    if(tid == 0) g_fmt = a32 ? 1 : (a16 ? 2 : 0);
}

// ---- weight convert -> e4m3 bytes (exact) ----
__global__ void k_convert(const void* __restrict__ src, uint8_t* __restrict__ dst, size_t n){
    int fmt = g_fmt;
    size_t i = (size_t)blockIdx.x*blockDim.x + threadIdx.x;
    size_t stride = (size_t)gridDim.x*blockDim.x;
    if(fmt == 1){
        const float4* s = (const float4*)src;
        size_t n4 = n >> 2;
        for(size_t j = i; j < n4; j += stride){
            float4 v = s[j];
            uchar4 o;
            o.x = (uint8_t)__nv_cvt_float_to_fp8(v.x, __NV_SATFINITE, __NV_E4M3);
            o.y = (uint8_t)__nv_cvt_float_to_fp8(v.y, __NV_SATFINITE, __NV_E4M3);
            o.z = (uint8_t)__nv_cvt_float_to_fp8(v.z, __NV_SATFINITE, __NV_E4M3);
            o.w = (uint8_t)__nv_cvt_float_to_fp8(v.w, __NV_SATFINITE, __NV_E4M3);
            ((uchar4*)dst)[j] = o;
        }
    } else if(fmt == 2){
        const uint2* s = (const uint2*)src;
        size_t n4 = n >> 2;
        for(size_t j = i; j < n4; j += stride){
            uint2 u = s[j];
            __nv_bfloat16 h[4];
            *(uint2*)h = u;
            uchar4 o;
            o.x = (uint8_t)__nv_cvt_float_to_fp8(__bfloat162float(h[0]), __NV_SATFINITE, __NV_E4M3);
            o.y = (uint8_t)__nv_cvt_float_to_fp8(__bfloat162float(h[1]), __NV_SATFINITE, __NV_E4M3);
            o.z = (uint8_t)__nv_cvt_float_to_fp8(__bfloat162float(h[2]), __NV_SATFINITE, __NV_E4M3);
            o.w = (uint8_t)__nv_cvt_float_to_fp8(__bfloat162float(h[3]), __NV_SATFINITE, __NV_E4M3);
            ((uchar4*)dst)[j] = o;
        }
    } else {
        const uint4* s = (const uint4*)src;
        size_t n16 = n >> 4;
        for(size_t j = i; j < n16; j += stride) ((uint4*)dst)[j] = s[j];
    }
}

// ---- activation fake-quant -> fp8 bytes + scale ----
__global__ void k_quant_x(const float* __restrict__ x, uint8_t* __restrict__ xq,
                          float* __restrict__ xs){
    int gidx = (int)(((size_t)blockIdx.x*blockDim.x + threadIdx.x) >> 5);
    int lane = threadIdx.x & 31;
    if(gidx >= M_DIM*KB_H) return;
    int row = gidx / KB_H, g = gidx % KB_H;
    float4 v = ((const float4*)(x + (size_t)row*H_DIM + g*128))[lane];
    float am = fmaxf(fmaxf(fabsf(v.x),fabsf(v.y)), fmaxf(fabsf(v.z),fabsf(v.w)));
#pragma unroll
    for(int o = 16; o; o >>= 1) am = fmaxf(am, __shfl_xor_sync(0xffffffffu, am, o));
    float s = fmaxf(__fdiv_rn(am, 448.0f), 1e-12f);
    uchar4 o;
    o.x=fq8(v.x,s); o.y=fq8(v.y,s); o.z=fq8(v.z,s); o.w=fq8(v.w,s);
    ((uchar4*)(xq + (size_t)row*H_DIM + g*128))[lane] = o;
    if(lane == 0) xs[(size_t)row*KB_H + g] = s;
}

// ---- SwiGLU + fake-quant of hidden -> fp8 bytes + scale ----
__global__ void k_swiglu(const float* __restrict__ gate, const float* __restrict__ up,
                         uint8_t* __restrict__ hq, float* __restrict__ hs){
    int gidx = (int)(((size_t)blockIdx.x*blockDim.x + threadIdx.x) >> 5);
    int lane = threadIdx.x & 31;
    if(gidx >= M_DIM*KB_I) return;
    int row = gidx / KB_I, g = gidx % KB_I;
    size_t base = (size_t)row*I_DIM + g*128;
    float4 gv = ((const float4*)(gate + base))[lane];
    float4 uv = ((const float4*)(up + base))[lane];
    float4 v;
    v.x = gv.x * sigmoid_precise(gv.x) * uv.x;
    v.y = gv.y * sigmoid_precise(gv.y) * uv.y;
    v.z = gv.z * sigmoid_precise(gv.z) * uv.z;
    v.w = gv.w * sigmoid_precise(gv.w) * uv.w;
    float am = fmaxf(fmaxf(fabsf(v.x),fabsf(v.y)), fmaxf(fabsf(v.z),fabsf(v.w)));
#pragma unroll
    for(int o = 16; o; o >>= 1) am = fmaxf(am, __shfl_xor_sync(0xffffffffu, am, o));
    float s = fmaxf(__fdiv_rn(am, 448.0f), 1e-12f);
    uchar4 o;
    o.x=fq8(v.x,s); o.y=fq8(v.y,s); o.z=fq8(v.z,s); o.w=fq8(v.w,s);
    ((uchar4*)(hq + base))[lane] = o;
    if(lane == 0) hs[(size_t)row*KB_I + g] = s;
}

// ---- fp8 block-scaled GEMM: out[M,N] = (Aq*As) @ (W*Ws)^T ----
// 128x128 CTA tile, 8 warps (4m x 2n; warp = 32m x 64n), K chunks of 128
// (= one scale block) double-buffered via cp.async. Per-chunk fp32 scale fold.
#define SMSB 144   // smem row stride in bytes (128 data + 16 pad): bank = (36q+r)%32, conflict-free
__global__ void __launch_bounds__(256, 1)
k_gemm8(const uint8_t* __restrict__ Aq, const float* __restrict__ As,
        const uint8_t* __restrict__ W,  const float* __restrict__ Ws,
        float* __restrict__ out, int M, int N, int K){
    extern __shared__ uint8_t sm8[];
    uint8_t* sA = sm8;                   // [2][128*SMSB]
    uint8_t* sB = sm8 + 2*128*SMSB;      // [2][128*SMSB]
    const int tid = threadIdx.x;
    const int wid = tid >> 5, lane = tid & 31;
    const int q = lane >> 2, r = lane & 3;
    const int wm = wid & 3, wn = wid >> 2;
    const int m0 = blockIdx.y*128, n0 = blockIdx.x*128;
    const int KS = K >> 7, NK = K >> 7;

    float acc[2][8][4];
#pragma unroll
    for(int a=0;a<2;a++)
#pragma unroll
        for(int b=0;b<8;b++)
#pragma unroll
            for(int c=0;c<4;c++) acc[a][b][c]=0.f;

    // prefetch chunk 0
#pragma unroll
    for(int i=0;i<8;i++){
        int idx = tid + i*256;
        int isB = idx >> 10, rem = idx & 1023;
        int row = rem >> 3, u = rem & 7;
        uint8_t* dst = (isB ? sB : sA) + row*SMSB + u*16;
        const uint8_t* src = (isB ? W + (size_t)(n0+row)*K : Aq + (size_t)(m0+row)*K) + u*16;
        cpasync16(dst, src);
    }
    asm volatile("cp.async.commit_group;\n");

    for(int kc = 0; kc < NK; kc++){
        int buf = kc & 1;
        asm volatile("cp.async.wait_group 0;\n");
        __syncthreads();
        if(kc + 1 < NK){
            int nb = buf ^ 1;
            int ko = (kc+1)*128;
#pragma unroll
            for(int i=0;i<8;i++){
                int idx = tid + i*256;
                int isB = idx >> 10, rem = idx & 1023;
                int row = rem >> 3, u = rem & 7;
                uint8_t* dst = (isB ? sB : sA) + nb*128*SMSB + row*SMSB + u*16;
                const uint8_t* src = (isB ? W + (size_t)(n0+row)*K : Aq + (size_t)(m0+row)*K) + ko + u*16;
                cpasync16(dst, src);
            }
            asm volatile("cp.async.commit_group;\n");
        }
        const uint8_t* bA = sA + buf*128*SMSB;
        const uint8_t* bB = sB + buf*128*SMSB;
        float part[2][8][4];
#pragma unroll
        for(int a=0;a<2;a++)
#pragma unroll
            for(int b=0;b<8;b++)
#pragma unroll
                for(int c=0;c<4;c++) part[a][b][c]=0.f;
#pragma unroll
        for(int ks = 0; ks < 4; ks++){
            int ko = ks*32;
            unsigned a[2][4], b[8][2];
#pragma unroll
            for(int mi=0;mi<2;mi++){
                const uint8_t* ap = bA + (wm*32 + mi*16 + q)*SMSB + ko + r*4;
                a[mi][0] = *(const unsigned*)ap;
                a[mi][1] = *(const unsigned*)(ap + 8*SMSB);
                a[mi][2] = *(const unsigned*)(ap + 16);
                a[mi][3] = *(const unsigned*)(ap + 8*SMSB + 16);
            }
#pragma unroll
            for(int ni=0;ni<8;ni++){
                const uint8_t* bp = bB + (wn*64 + ni*8 + q)*SMSB + ko + r*4;
                b[ni][0] = *(const unsigned*)bp;
                b[ni][1] = *(const unsigned*)(bp + 16);
            }
#pragma unroll
            for(int mi=0;mi<2;mi++)
#pragma unroll
                for(int ni=0;ni<8;ni++)
                    mma8(part[mi][ni], a[mi], b[ni]);
        }
        // fold scales (one scale block per 128-K chunk)
        {
            float sw = Ws[(size_t)blockIdx.x*KS + kc];
#pragma unroll
            for(int mi=0;mi<2;mi++){
                int r0 = m0 + wm*32 + mi*16 + q;
                float s0 = As[(size_t)r0*KS + kc] * sw;
                float s1 = As[(size_t)(r0+8)*KS + kc] * sw;
#pragma unroll
                for(int ni=0;ni<8;ni++){
                    acc[mi][ni][0] = fmaf(part[mi][ni][0], s0, acc[mi][ni][0]);
                    acc[mi][ni][1] = fmaf(part[mi][ni][1], s0, acc[mi][ni][1]);
                    acc[mi][ni][2] = fmaf(part[mi][ni][2], s1, acc[mi][ni][2]);
                    acc[mi][ni][3] = fmaf(part[mi][ni][3], s1, acc[mi][ni][3]);
                }
            }
        }
        __syncthreads();
    }
    // epilogue
#pragma unroll
    for(int mi=0;mi<2;mi++){
        int r0 = m0 + wm*32 + mi*16 + q;
#pragma unroll
        for(int ni=0;ni<8;ni++){
            int c = n0 + wn*64 + ni*8 + r*2;
            *(float2*)(out + (size_t)r0*N + c)     = make_float2(acc[mi][ni][0], acc[mi][ni][1]);
            *(float2*)(out + (size_t)(r0+8)*N + c) = make_float2(acc[mi][ni][2], acc[mi][ni][3]);
        }
    }
}

extern "C" void kernel_launch(void* const* d_in, const int* in_sizes, int n_in,
                              void* d_out, int out_size){
    const float* x = (const float*)d_in[0];
    const void*  wg = d_in[1]; const float* wgs = (const float*)d_in[2];
    const void*  wu = d_in[3]; const float* wus = (const float*)d_in[4];
    const void*  wd = d_in[5]; const float* wds = (const float*)d_in[6];
    float* out = (float*)d_out;

    uint8_t *p_wg, *p_wu, *p_wd, *p_xq, *p_hq;
    float *p_xs, *p_gate, *p_up, *p_hs;
    cudaGetSymbolAddress((void**)&p_wg, g_wg);
    cudaGetSymbolAddress((void**)&p_wu, g_wu);
    cudaGetSymbolAddress((void**)&p_wd, g_wd);
    cudaGetSymbolAddress((void**)&p_xq, g_xq);
    cudaGetSymbolAddress((void**)&p_xs, g_xs);
    cudaGetSymbolAddress((void**)&p_gate, g_gate);
    cudaGetSymbolAddress((void**)&p_up, g_up);
    cudaGetSymbolAddress((void**)&p_hq, g_hq);
    cudaGetSymbolAddress((void**)&p_hs, g_hs);

    static bool attr_set = false;
    const int smem_sz = 2*2*128*SMSB; // 73728 B
    if(!attr_set){
        cudaFuncSetAttribute(k_gemm8, cudaFuncAttributeMaxDynamicSharedMemorySize, smem_sz);
        attr_set = true;
    }

    k_detect<<<1, 256>>>(wg);
    k_convert<<<4096, 256>>>(wg, p_wg, (size_t)I_DIM*H_DIM);
    k_convert<<<4096, 256>>>(wu, p_wu, (size_t)I_DIM*H_DIM);
    k_convert<<<4096, 256>>>(wd, p_wd, (size_t)H_DIM*I_DIM);

    k_quant_x<<<(M_DIM*KB_H)/8, 256>>>(x, p_xq, p_xs);

    dim3 gGU(I_DIM/128, M_DIM/128);
    k_gemm8<<<gGU, 256, smem_sz>>>(p_xq, p_xs, p_wg, wgs, p_gate, M_DIM, I_DIM, H_DIM);
    k_gemm8<<<gGU, 256, smem_sz>>>(p_xq, p_xs, p_wu, wus, p_up,   M_DIM, I_DIM, H_DIM);

    k_swiglu<<<(M_DIM*KB_I)/8, 256>>>(p_gate, p_up, p_hq, p_hs);

    dim3 gD(H_DIM/128, M_DIM/128);
    k_gemm8<<<gD, 256, smem_sz>>>(p_hq, p_hs, p_wd, wds, out, M_DIM, H_DIM, I_DIM);
}

// round 5
// speedup vs baseline: 1.2967x; 1.2967x over previous
#include <cuda_runtime.h>
#include <cuda_bf16.h>
#include <cuda_fp8.h>
#include <cstdint>

#define M_DIM 4096
#define H_DIM 4096
#define I_DIM 14336
#define KB_H (H_DIM/128)
#define KB_I (I_DIM/128)

// ---- static scratch ----
__device__ int g_fmt;
__device__ __nv_bfloat16 g_wg[(size_t)I_DIM*H_DIM];
__device__ __nv_bfloat16 g_wu[(size_t)I_DIM*H_DIM];
__device__ __nv_bfloat16 g_wd[(size_t)H_DIM*I_DIM];
__device__ __nv_bfloat16 g_xq[(size_t)M_DIM*H_DIM];
__device__ float         g_xs[(size_t)M_DIM*KB_H];
__device__ __nv_bfloat16 g_hq[(size_t)M_DIM*I_DIM];
__device__ float         g_hs[(size_t)M_DIM*KB_I];

// ---- scalar helpers ----
__device__ __forceinline__ float fp8_to_f32(unsigned char b){
    __half_raw hr = __nv_cvt_fp8_to_halfraw((__nv_fp8_storage_t)b, __NV_E4M3);
    return __half2float(*(__half*)&hr);
}
__device__ __forceinline__ bool fp8_rt(float v){
    if(!isfinite(v) || fabsf(v) > 448.0f) return false;
    __nv_fp8_storage_t b = __nv_cvt_float_to_fp8(v, __NV_SATFINITE, __NV_E4M3);
    return fp8_to_f32((unsigned char)b) == v;
}
__device__ __forceinline__ __nv_bfloat16 fq1(float v, float s){
    float d = __fdiv_rn(v, s);
    __nv_fp8_storage_t b = __nv_cvt_float_to_fp8(d, __NV_SATFINITE, __NV_E4M3);
    return __float2bfloat16(fp8_to_f32((unsigned char)b));
}
__device__ __forceinline__ float exp_precise(float x){
    float n = rintf(x * 1.4426950408889634f);
    float r = fmaf(n, -0.693359375f, x);
    r = fmaf(n, 2.12194440e-4f, r);
    float p = 1.9841269841e-4f;
    p = fmaf(p, r, 1.3888888888e-3f);
    p = fmaf(p, r, 8.3333333333e-3f);
    p = fmaf(p, r, 4.1666666667e-2f);
    p = fmaf(p, r, 1.6666666667e-1f);
    p = fmaf(p, r, 0.5f);
    p = fmaf(p, r, 1.0f);
    p = fmaf(p, r, 1.0f);
    return ldexpf(p, (int)n);
}
__device__ __forceinline__ float sigmoid_precise(float x){
    float ax = fminf(fabsf(x), 87.0f);
    float e = exp_precise(-ax);
    float den = 1.0f + e;
    return (x >= 0.0f) ? __fdiv_rn(1.0f, den) : __fdiv_rn(e, den);
}
__device__ __forceinline__ void cpasync16(void* s, const void* g){
    unsigned sa = (unsigned)__cvta_generic_to_shared(s);
    asm volatile("cp.async.cg.shared.global [%0], [%1], 16;\n" :: "r"(sa), "l"(g));
}
__device__ __forceinline__ void mma16816(float* c, const unsigned* a, const unsigned* b){
    asm volatile("mma.sync.aligned.m16n8k16.row.col.f32.bf16.bf16.f32 "
        "{%0,%1,%2,%3}, {%4,%5,%6,%7}, {%8,%9}, {%0,%1,%2,%3};\n"
        : "+f"(c[0]), "+f"(c[1]), "+f"(c[2]), "+f"(c[3])
        : "r"(a[0]), "r"(a[1]), "r"(a[2]), "r"(a[3]), "r"(b[0]), "r"(b[1]));
}

// ---- format detection ----
__global__ void k_detect(const void* __restrict__ w){
    int tid = threadIdx.x;
    int ok32 = 1, ok16 = 1;
    for(int i = tid; i < 2048; i += blockDim.x){
        ok32 = ok32 && fp8_rt(((const float*)w)[i]);
        ok16 = ok16 && fp8_rt(__bfloat162float(((const __nv_bfloat16*)w)[i]));
    }
    int a32 = __syncthreads_and(ok32);
    int a16 = __syncthreads_and(ok16);
    if(tid == 0) g_fmt = a32 ? 1 : (a16 ? 2 : 0);
}

// ---- weight convert -> bf16 (exact) ----
__global__ void k_convert(const void* __restrict__ src, __nv_bfloat16* __restrict__ dst, size_t n){
    int fmt = g_fmt;
    size_t i = (size_t)blockIdx.x*blockDim.x + threadIdx.x;
    size_t stride = (size_t)gridDim.x*blockDim.x;
    size_t n4 = n >> 2;
    if(fmt == 1){
        const float4* s = (const float4*)src;
        for(size_t j = i; j < n4; j += stride){
            float4 v = s[j];
            union{ __nv_bfloat16 h[4]; uint2 u; } o;
            o.h[0]=__float2bfloat16(v.x); o.h[1]=__float2bfloat16(v.y);
            o.h[2]=__float2bfloat16(v.z); o.h[3]=__float2bfloat16(v.w);
            ((uint2*)dst)[j] = o.u;
        }
    } else if(fmt == 2){
        const uint2* s = (const uint2*)src;
        for(size_t j = i; j < n4; j += stride) ((uint2*)dst)[j] = s[j];
    } else {
        const uchar4* s = (const uchar4*)src;
        for(size_t j = i; j < n4; j += stride){
            uchar4 v = s[j];
            union{ __nv_bfloat16 h[4]; uint2 u; } o;
            o.h[0]=__float2bfloat16(fp8_to_f32(v.x));
            o.h[1]=__float2bfloat16(fp8_to_f32(v.y));
            o.h[2]=__float2bfloat16(fp8_to_f32(v.z));
            o.h[3]=__float2bfloat16(fp8_to_f32(v.w));
            ((uint2*)dst)[j] = o.u;
        }
    }
}

// ---- activation fake-quant ----
__global__ void k_quant_x(const float* __restrict__ x, __nv_bfloat16* __restrict__ xq,
                          float* __restrict__ xs){
    int gidx = (int)(((size_t)blockIdx.x*blockDim.x + threadIdx.x) >> 5);
    int lane = threadIdx.x & 31;
    if(gidx >= M_DIM*KB_H) return;
    int row = gidx / KB_H, g = gidx % KB_H;
    float4 v = ((const float4*)(x + (size_t)row*H_DIM + g*128))[lane];
    float am = fmaxf(fmaxf(fabsf(v.x),fabsf(v.y)), fmaxf(fabsf(v.z),fabsf(v.w)));
#pragma unroll
    for(int o = 16; o; o >>= 1) am = fmaxf(am, __shfl_xor_sync(0xffffffffu, am, o));
    float s = fmaxf(__fdiv_rn(am, 448.0f), 1e-12f);
    union{ __nv_bfloat16 h[4]; uint2 u; } o;
    o.h[0]=fq1(v.x,s); o.h[1]=fq1(v.y,s); o.h[2]=fq1(v.z,s); o.h[3]=fq1(v.w,s);
    ((uint2*)(xq + (size_t)row*H_DIM + g*128))[lane] = o.u;
    if(lane == 0) xs[(size_t)row*KB_H + g] = s;
}

// =====================================================================
// Shared GEMM machinery: 128x128 CTA tile, 8 warps (4m x 2n, warp 32x64),
// K-chunk = 128 (one scale block), double-buffered cp.async, smem row
// stride 136 halves (272B) — conflict-free frag loads.
// =====================================================================
#define SMSH 136
#define BUFB (128*SMSH*2)   // 34816 bytes per buffer per matrix

// one K-chunk of MMAs for one B matrix: part += Asmem * Bsmem^T (exact)
__device__ __forceinline__ void chunk_mma(const __nv_bfloat16* bA, const __nv_bfloat16* bB,
                                          int wm, int wn, int q, int r, float part[2][8][4]){
#pragma unroll
    for(int ks = 0; ks < 8; ks++){
        int ko = ks*16;
        unsigned a[2][4], b[8][2];
#pragma unroll
        for(int mi=0;mi<2;mi++){
            const __nv_bfloat16* ap = bA + (wm*32 + mi*16 + q)*SMSH + ko + r*2;
            a[mi][0] = *(const unsigned*)ap;
            a[mi][1] = *(const unsigned*)(ap + 8*SMSH);
            a[mi][2] = *(const unsigned*)(ap + 8);
            a[mi][3] = *(const unsigned*)(ap + 8*SMSH + 8);
        }
#pragma unroll
        for(int ni=0;ni<8;ni++){
            const __nv_bfloat16* bp = bB + (wn*64 + ni*8 + q)*SMSH + ko + r*2;
            b[ni][0] = *(const unsigned*)bp;
            b[ni][1] = *(const unsigned*)(bp + 8);
        }
#pragma unroll
        for(int mi=0;mi<2;mi++)
#pragma unroll
            for(int ni=0;ni<8;ni++)
                mma16816(part[mi][ni], a[mi], b[ni]);
    }
}

__device__ __forceinline__ void fold(float part[2][8][4], float acc[2][8][4],
                                     const float* As, const float* wsr, int kc, int KS,
                                     int m0, int wm, int q){
    float sw = wsr[kc];
#pragma unroll
    for(int mi=0;mi<2;mi++){
        int r0 = m0 + wm*32 + mi*16 + q;
        float s0 = As[(size_t)r0*KS + kc] * sw;
        float s1 = As[(size_t)(r0+8)*KS + kc] * sw;
#pragma unroll
        for(int ni=0;ni<8;ni++){
            acc[mi][ni][0] = fmaf(part[mi][ni][0], s0, acc[mi][ni][0]);
            acc[mi][ni][1] = fmaf(part[mi][ni][1], s0, acc[mi][ni][1]);
            acc[mi][ni][2] = fmaf(part[mi][ni][2], s1, acc[mi][ni][2]);
            acc[mi][ni][3] = fmaf(part[mi][ni][3], s1, acc[mi][ni][3]);
        }
    }
}

// ---- fused gate+up GEMM + SwiGLU + hidden quant ----
// grid: (M/128, I/128)  (x = m-tile fastest so concurrent CTAs share B tiles)
__global__ void __launch_bounds__(256, 1)
k_gemm_gu(const __nv_bfloat16* __restrict__ Aq, const float* __restrict__ As,
          const __nv_bfloat16* __restrict__ Wg, const float* __restrict__ Wsg,
          const __nv_bfloat16* __restrict__ Wu, const float* __restrict__ Wsu,
          __nv_bfloat16* __restrict__ hq, float* __restrict__ hs){
    extern __shared__ uint8_t sm8[];
    const int K = H_DIM, KS = KB_H, NK = KB_H;
    const int tid = threadIdx.x, wid = tid>>5, lane = tid&31;
    const int q = lane>>2, r = lane&3;
    const int wm = wid&3, wn = wid>>2;
    const int m0 = blockIdx.x<<7, n0 = blockIdx.y<<7;
    const float* wsgr = Wsg + (size_t)blockIdx.y*KS;
    const float* wsur = Wsu + (size_t)blockIdx.y*KS;

    uint8_t* sA  = sm8;
    uint8_t* sBg = sm8 + 2*BUFB;
    uint8_t* sBu = sm8 + 4*BUFB;

    float accG[2][8][4], accU[2][8][4];
#pragma unroll
    for(int a=0;a<2;a++)
#pragma unroll
        for(int b=0;b<8;b++)
#pragma unroll
            for(int c=0;c<4;c++){ accG[a][b][c]=0.f; accU[a][b][c]=0.f; }

    // fill(chunk kc, buf)
    auto fill = [&](int kc, int buf){
#pragma unroll
        for(int j=0;j<24;j++){
            int idx = tid + j*256;
            int mat = idx >> 11, rem = idx & 2047;
            int row = rem >> 4, u = rem & 15;
            uint8_t* base = (mat==0) ? sA : (mat==1) ? sBg : sBu;
            const __nv_bfloat16* g = (mat==0) ? Aq + (size_t)(m0+row)*K
                                   : (mat==1) ? Wg + (size_t)(n0+row)*K
                                              : Wu + (size_t)(n0+row)*K;
            cpasync16(base + buf*BUFB + row*(SMSH*2) + u*16,
                      (const uint8_t*)(g + kc*128) + u*16);
        }
        asm volatile("cp.async.commit_group;\n");
    };

    fill(0, 0);
    for(int kc = 0; kc < NK; kc++){
        int buf = kc & 1;
        asm volatile("cp.async.wait_group 0;\n");
        __syncthreads();
        if(kc + 1 < NK) fill(kc+1, buf^1);

        const __nv_bfloat16* bA  = (const __nv_bfloat16*)(sA  + buf*BUFB);
        const __nv_bfloat16* bBg = (const __nv_bfloat16*)(sBg + buf*BUFB);
        const __nv_bfloat16* bBu = (const __nv_bfloat16*)(sBu + buf*BUFB);

        float part[2][8][4];
#pragma unroll
        for(int a=0;a<2;a++)
#pragma unroll
            for(int b=0;b<8;b++)
#pragma unroll
                for(int c=0;c<4;c++) part[a][b][c]=0.f;
        chunk_mma(bA, bBg, wm, wn, q, r, part);
        fold(part, accG, As, wsgr, kc, KS, m0, wm, q);
#pragma unroll
        for(int a=0;a<2;a++)
#pragma unroll
            for(int b=0;b<8;b++)
#pragma unroll
                for(int c=0;c<4;c++) part[a][b][c]=0.f;
        chunk_mma(bA, bBu, wm, wn, q, r, part);
        fold(part, accU, As, wsur, kc, KS, m0, wm, q);
        __syncthreads();
    }

    // ---- epilogue: h = silu(gate)*up, per-row amax over this 128-col group,
    // quantize, write hq (bf16-exact fp8 values) + hs ----
#pragma unroll
    for(int mi=0;mi<2;mi++)
#pragma unroll
        for(int ni=0;ni<8;ni++)
#pragma unroll
            for(int c=0;c<4;c++){
                float g = accG[mi][ni][c];
                accG[mi][ni][c] = g * sigmoid_precise(g) * accU[mi][ni][c];
            }
    float* red = (float*)sm8;   // [2][128] (safe: pipeline drained)
#pragma unroll
    for(int mi=0;mi<2;mi++){
        float a0 = 0.f, a1 = 0.f;
#pragma unroll
        for(int ni=0;ni<8;ni++){
            a0 = fmaxf(a0, fmaxf(fabsf(accG[mi][ni][0]), fabsf(accG[mi][ni][1])));
            a1 = fmaxf(a1, fmaxf(fabsf(accG[mi][ni][2]), fabsf(accG[mi][ni][3])));
        }
        a0 = fmaxf(a0, __shfl_xor_sync(0xffffffffu, a0, 1));
        a0 = fmaxf(a0, __shfl_xor_sync(0xffffffffu, a0, 2));
        a1 = fmaxf(a1, __shfl_xor_sync(0xffffffffu, a1, 1));
        a1 = fmaxf(a1, __shfl_xor_sync(0xffffffffu, a1, 2));
        if(r == 0){
            int rl = wm*32 + mi*16 + q;
            red[wn*128 + rl] = a0;
            red[wn*128 + rl + 8] = a1;
        }
    }
    __syncthreads();
    const int gidx = blockIdx.y;
#pragma unroll
    for(int mi=0;mi<2;mi++){
        int rl0 = wm*32 + mi*16 + q;
        float am0 = fmaxf(red[rl0], red[128+rl0]);
        float am1 = fmaxf(red[rl0+8], red[128+rl0+8]);
        float s0 = fmaxf(__fdiv_rn(am0, 448.0f), 1e-12f);
        float s1 = fmaxf(__fdiv_rn(am1, 448.0f), 1e-12f);
        if(wn == 0 && r == 0){
            hs[(size_t)(m0+rl0)*KB_I + gidx] = s0;
            hs[(size_t)(m0+rl0+8)*KB_I + gidx] = s1;
        }
#pragma unroll
        for(int ni=0;ni<8;ni++){
            int c = n0 + wn*64 + ni*8 + r*2;
            union{ __nv_bfloat16 h[2]; unsigned u; } o;
            o.h[0] = fq1(accG[mi][ni][0], s0);
            o.h[1] = fq1(accG[mi][ni][1], s0);
            *(unsigned*)(hq + (size_t)(m0+rl0)*I_DIM + c) = o.u;
            o.h[0] = fq1(accG[mi][ni][2], s1);
            o.h[1] = fq1(accG[mi][ni][3], s1);
            *(unsigned*)(hq + (size_t)(m0+rl0+8)*I_DIM + c) = o.u;
        }
    }
}

// ---- down GEMM: out = (hq*hs) @ (Wd*Wsd)^T ----
// grid: (M/128, H/128), x = m-tile fastest
__global__ void __launch_bounds__(256, 1)
k_gemm_dn(const __nv_bfloat16* __restrict__ Aq, const float* __restrict__ As,
          const __nv_bfloat16* __restrict__ W,  const float* __restrict__ Ws,
          float* __restrict__ out){
    extern __shared__ uint8_t sm8[];
    const int K = I_DIM, KS = KB_I, NK = KB_I, N = H_DIM;
    const int tid = threadIdx.x, wid = tid>>5, lane = tid&31;
    const int q = lane>>2, r = lane&3;
    const int wm = wid&3, wn = wid>>2;
    const int m0 = blockIdx.x<<7, n0 = blockIdx.y<<7;
    const float* wsr = Ws + (size_t)blockIdx.y*KS;

    uint8_t* sA = sm8;
    uint8_t* sB = sm8 + 2*BUFB;

    float acc[2][8][4];
#pragma unroll
    for(int a=0;a<2;a++)
#pragma unroll
        for(int b=0;b<8;b++)
#pragma unroll
            for(int c=0;c<4;c++) acc[a][b][c]=0.f;

    auto fill = [&](int kc, int buf){
#pragma unroll
        for(int j=0;j<16;j++){
            int idx = tid + j*256;
            int mat = idx >> 11, rem = idx & 2047;
            int row = rem >> 4, u = rem & 15;
            uint8_t* base = mat ? sB : sA;
            const __nv_bfloat16* g = mat ? W + (size_t)(n0+row)*K : Aq + (size_t)(m0+row)*K;
            cpasync16(base + buf*BUFB + row*(SMSH*2) + u*16,
                      (const uint8_t*)(g + kc*128) + u*16);
        }
        asm volatile("cp.async.commit_group;\n");
    };

    fill(0, 0);
    for(int kc = 0; kc < NK; kc++){
        int buf = kc & 1;
        asm volatile("cp.async.wait_group 0;\n");
        __syncthreads();
        if(kc + 1 < NK) fill(kc+1, buf^1);
        const __nv_bfloat16* bA = (const __nv_bfloat16*)(sA + buf*BUFB);
        const __nv_bfloat16* bB = (const __nv_bfloat16*)(sB + buf*BUFB);
        float part[2][8][4];
#pragma unroll
        for(int a=0;a<2;a++)
#pragma unroll
            for(int b=0;b<8;b++)
#pragma unroll
                for(int c=0;c<4;c++) part[a][b][c]=0.f;
        chunk_mma(bA, bB, wm, wn, q, r, part);
        fold(part, acc, As, wsr, kc, KS, m0, wm, q);
        __syncthreads();
    }
#pragma unroll
    for(int mi=0;mi<2;mi++){
        int r0 = m0 + wm*32 + mi*16 + q;
#pragma unroll
        for(int ni=0;ni<8;ni++){
            int c = n0 + wn*64 + ni*8 + r*2;
            *(float2*)(out + (size_t)r0*N + c)     = make_float2(acc[mi][ni][0], acc[mi][ni][1]);
            *(float2*)(out + (size_t)(r0+8)*N + c) = make_float2(acc[mi][ni][2], acc[mi][ni][3]);
        }
    }
}

extern "C" void kernel_launch(void* const* d_in, const int* in_sizes, int n_in,
                              void* d_out, int out_size){
    const float* x = (const float*)d_in[0];
    const void*  wg = d_in[1]; const float* wgs = (const float*)d_in[2];
    const void*  wu = d_in[3]; const float* wus = (const float*)d_in[4];
    const void*  wd = d_in[5]; const float* wds = (const float*)d_in[6];
    float* out = (float*)d_out;

    __nv_bfloat16 *p_wg, *p_wu, *p_wd, *p_xq, *p_hq;
    float *p_xs, *p_hs;
    cudaGetSymbolAddress((void**)&p_wg, g_wg);
    cudaGetSymbolAddress((void**)&p_wu, g_wu);
    cudaGetSymbolAddress((void**)&p_wd, g_wd);
    cudaGetSymbolAddress((void**)&p_xq, g_xq);
    cudaGetSymbolAddress((void**)&p_xs, g_xs);
    cudaGetSymbolAddress((void**)&p_hq, g_hq);
    cudaGetSymbolAddress((void**)&p_hs, g_hs);

    static bool attr_set = false;
    const int smem_gu = 6*BUFB;  // 208896
    const int smem_dn = 4*BUFB;  // 139264
    if(!attr_set){
        cudaFuncSetAttribute(k_gemm_gu, cudaFuncAttributeMaxDynamicSharedMemorySize, smem_gu);
        cudaFuncSetAttribute(k_gemm_dn, cudaFuncAttributeMaxDynamicSharedMemorySize, smem_dn);
        attr_set = true;
    }

    k_detect<<<1, 256>>>(wg);
    k_convert<<<4096, 256>>>(wg, p_wg, (size_t)I_DIM*H_DIM);
    k_convert<<<4096, 256>>>(wu, p_wu, (size_t)I_DIM*H_DIM);
    k_convert<<<4096, 256>>>(wd, p_wd, (size_t)H_DIM*I_DIM);

    k_quant_x<<<(M_DIM*KB_H)/8, 256>>>(x, p_xq, p_xs);

    dim3 gGU(M_DIM/128, I_DIM/128);
    k_gemm_gu<<<gGU, 256, smem_gu>>>(p_xq, p_xs, p_wg, wgs, p_wu, wus, p_hq, p_hs);

    dim3 gD(M_DIM/128, H_DIM/128);
    k_gemm_dn<<<gD, 256, smem_dn>>>(p_hq, p_hs, p_wd, wds, out);
}

// round 9
// speedup vs baseline: 1.6346x; 1.2606x over previous
#include <cuda_runtime.h>
#include <cuda_bf16.h>
#include <cuda_fp8.h>
#include <cstdint>

#define M_DIM 4096
#define H_DIM 4096
#define I_DIM 14336
#define KB_H (H_DIM/128)
#define KB_I (I_DIM/128)

// ---- static scratch (all quantized tensors as permuted e4m3 bytes) ----
__device__ int g_fmt;
__device__ uint8_t g_wg[(size_t)I_DIM*H_DIM];
__device__ uint8_t g_wu[(size_t)I_DIM*H_DIM];
__device__ uint8_t g_wd[(size_t)H_DIM*I_DIM];
__device__ uint8_t g_xq[(size_t)M_DIM*H_DIM];
__device__ float   g_xs[(size_t)M_DIM*KB_H];
__device__ uint8_t g_hq[(size_t)M_DIM*I_DIM];
__device__ float   g_hs[(size_t)M_DIM*KB_I];

// ---- scalar helpers ----
__device__ __forceinline__ float fp8_to_f32(unsigned char b){
    __half_raw hr = __nv_cvt_fp8_to_halfraw((__nv_fp8_storage_t)b, __NV_E4M3);
    return __half2float(*(__half*)&hr);
}
__device__ __forceinline__ bool fp8_rt(float v){
    if(!isfinite(v) || fabsf(v) > 448.0f) return false;
    __nv_fp8_storage_t b = __nv_cvt_float_to_fp8(v, __NV_SATFINITE, __NV_E4M3);
    return fp8_to_f32((unsigned char)b) == v;
}
__device__ __forceinline__ uint32_t fq8(float v, float s){
    return (uint32_t)(uint8_t)__nv_cvt_float_to_fp8(__fdiv_rn(v, s), __NV_SATFINITE, __NV_E4M3);
}
__device__ __forceinline__ uint32_t f2e4m3(float v){
    return (uint32_t)(uint8_t)__nv_cvt_float_to_fp8(v, __NV_SATFINITE, __NV_E4M3);
}
__device__ __forceinline__ float exp_precise(float x){
    float n = rintf(x * 1.4426950408889634f);
    float r = fmaf(n, -0.693359375f, x);
    r = fmaf(n, 2.12194440e-4f, r);
    float p = 1.9841269841e-4f;
    p = fmaf(p, r, 1.3888888888e-3f);
    p = fmaf(p, r, 8.3333333333e-3f);
    p = fmaf(p, r, 4.1666666667e-2f);
    p = fmaf(p, r, 1.6666666667e-1f);
    p = fmaf(p, r, 0.5f);
    p = fmaf(p, r, 1.0f);
    p = fmaf(p, r, 1.0f);
    return ldexpf(p, (int)n);
}
__device__ __forceinline__ float sigmoid_precise(float x){
    float ax = fminf(fabsf(x), 87.0f);
    float e = exp_precise(-ax);
    float den = 1.0f + e;
    return (x >= 0.0f) ? __fdiv_rn(1.0f, den) : __fdiv_rn(e, den);
}
__device__ __forceinline__ void cpasync16(void* s, const void* g){
    unsigned sa = (unsigned)__cvta_generic_to_shared(s);
    asm volatile("cp.async.cg.shared.global [%0], [%1], 16;\n" :: "r"(sa), "l"(g));
}
__device__ __forceinline__ unsigned cvt8(unsigned short s){
    unsigned r;
    asm("cvt.rn.f16x2.e4m3x2 %0, %1;" : "=r"(r) : "h"(s));
    return r;
}
__device__ __forceinline__ void mma_f16(float* c, unsigned a0, unsigned a1, unsigned a2, unsigned a3,
                                        unsigned b0, unsigned b1){
    asm volatile("mma.sync.aligned.m16n8k16.row.col.f32.f16.f16.f32 "
        "{%0,%1,%2,%3}, {%4,%5,%6,%7}, {%8,%9}, {%0,%1,%2,%3};\n"
        : "+f"(c[0]), "+f"(c[1]), "+f"(c[2]), "+f"(c[3])
        : "r"(a0), "r"(a1), "r"(a2), "r"(a3), "r"(b0), "r"(b1));
}
// permuted byte position of (even) col c within its 16-group
__device__ __forceinline__ int pj(int c){ return ((c&7)>>1)*4 + ((c>>3)<<1); }

// ---- format detection ----
__global__ void k_detect(const void* __restrict__ w){
    int tid = threadIdx.x;
    int ok32 = 1, ok16 = 1;
    for(int i = tid; i < 2048; i += blockDim.x){
        ok32 = ok32 && fp8_rt(((const float*)w)[i]);
        ok16 = ok16 && fp8_rt(__bfloat162float(((const __nv_bfloat16*)w)[i]));
    }
    int a32 = __syncthreads_and(ok32);
    int a16 = __syncthreads_and(ok16);
    if(tid == 0) g_fmt = a32 ? 1 : (a16 ? 2 : 0);
}

// ---- weight convert -> permuted e4m3 bytes (exact) ----
// output 32-bit word widx (group=widx>>2, r=widx&3) holds cols {2r,2r+1,2r+8,2r+9} of group
__global__ void k_convert(const void* __restrict__ src, uint8_t* __restrict__ dst, size_t n){
    int fmt = g_fmt;
    size_t i = (size_t)blockIdx.x*blockDim.x + threadIdx.x;
    size_t stride = (size_t)gridDim.x*blockDim.x;
    size_t nw = n >> 2;
    for(size_t widx = i; widx < nw; widx += stride){
        size_t cc = (widx >> 2) << 4;
        int r = (int)(widx & 3);
        uint32_t w;
        if(fmt == 1){
            const float* s = (const float*)src;
            float2 p0 = *(const float2*)(s + cc + 2*r);
            float2 p1 = *(const float2*)(s + cc + 2*r + 8);
            w = f2e4m3(p0.x) | (f2e4m3(p0.y)<<8) | (f2e4m3(p1.x)<<16) | (f2e4m3(p1.y)<<24);
        } else if(fmt == 2){
            const __nv_bfloat16* s = (const __nv_bfloat16*)src;
            __nv_bfloat16 h0[2], h1[2];
            *(uint32_t*)h0 = *(const uint32_t*)(s + cc + 2*r);
            *(uint32_t*)h1 = *(const uint32_t*)(s + cc + 2*r + 8);
            w = f2e4m3(__bfloat162float(h0[0])) | (f2e4m3(__bfloat162float(h0[1]))<<8)
              | (f2e4m3(__bfloat162float(h1[0]))<<16) | (f2e4m3(__bfloat162float(h1[1]))<<24);
        } else {
            const uint8_t* s = (const uint8_t*)src;
            uint32_t lo = *(const uint16_t*)(s + cc + 2*r);
            uint32_t hi = *(const uint16_t*)(s + cc + 2*r + 8);
            w = lo | (hi << 16);
        }
        ((uint32_t*)dst)[widx] = w;
    }
}

// ---- activation fake-quant -> permuted e4m3 bytes + scale ----
__global__ void k_quant_x(const float* __restrict__ x, uint8_t* __restrict__ xq,
                          float* __restrict__ xs){
    int gidx = (int)(((size_t)blockIdx.x*blockDim.x + threadIdx.x) >> 5);
    int lane = threadIdx.x & 31;
    if(gidx >= M_DIM*KB_H) return;
    int row = gidx / KB_H, g = gidx % KB_H;
    float4 v = ((const float4*)(x + (size_t)row*H_DIM + g*128))[lane];
    float am = fmaxf(fmaxf(fabsf(v.x),fabsf(v.y)), fmaxf(fabsf(v.z),fabsf(v.w)));
#pragma unroll
    for(int o = 16; o; o >>= 1) am = fmaxf(am, __shfl_xor_sync(0xffffffffu, am, o));
    float s = fmaxf(__fdiv_rn(am, 448.0f), 1e-12f);
    uint32_t q0 = fq8(v.x,s), q1 = fq8(v.y,s), q2 = fq8(v.z,s), q3 = fq8(v.w,s);
    int lc = (lane & 3) * 4;
    uint8_t* base = xq + (size_t)row*H_DIM + g*128 + (lane>>2)*16;
    *(uint16_t*)(base + pj(lc))   = (uint16_t)(q0 | (q1<<8));
    *(uint16_t*)(base + pj(lc+2)) = (uint16_t)(q2 | (q3<<8));
    if(lane == 0) xs[(size_t)row*KB_H + g] = s;
}

// =====================================================================
// GEMM machinery: 128x128 CTA tile, 8 warps (4m x 2n, warp 32x64),
// K-chunk = 128 elems = 128 bytes (one scale block), double-buffered
// cp.async, smem row stride 144 bytes. Operands: permuted e4m3 bytes,
// converted to exact fp16 fragments on load (LDS.32 + 2x cvt).
// =====================================================================
#define SMB 144
#define BUF (128*SMB)   // 18432 bytes per buffer per matrix

__device__ __forceinline__ void chunk_mma(const uint8_t* bA, const uint8_t* bB,
                                          int wm, int wn, int q, int r, float part[2][8][4]){
#pragma unroll
    for(int ks = 0; ks < 8; ks++){
        int ko = ks*16 + r*4;
        unsigned af[2][4], bf[8][2];
#pragma unroll
        for(int mi=0;mi<2;mi++){
            const uint8_t* ap = bA + (wm*32 + mi*16 + q)*SMB + ko;
            unsigned w0 = *(const unsigned*)ap;
            unsigned w1 = *(const unsigned*)(ap + 8*SMB);
            af[mi][0] = cvt8((unsigned short)w0);
            af[mi][2] = cvt8((unsigned short)(w0>>16));
            af[mi][1] = cvt8((unsigned short)w1);
            af[mi][3] = cvt8((unsigned short)(w1>>16));
        }
#pragma unroll
        for(int ni=0;ni<8;ni++){
            const uint8_t* bp = bB + (wn*64 + ni*8 + q)*SMB + ko;
            unsigned w = *(const unsigned*)bp;
            bf[ni][0] = cvt8((unsigned short)w);
            bf[ni][1] = cvt8((unsigned short)(w>>16));
        }
#pragma unroll
        for(int mi=0;mi<2;mi++)
#pragma unroll
            for(int ni=0;ni<8;ni++)
                mma_f16(part[mi][ni], af[mi][0], af[mi][1], af[mi][2], af[mi][3],
                        bf[ni][0], bf[ni][1]);
    }
}

__device__ __forceinline__ void fold(float part[2][8][4], float acc[2][8][4],
                                     const float* As, const float* wsr, int kc, int KS,
                                     int m0, int wm, int q){
    float sw = wsr[kc];
#pragma unroll
    for(int mi=0;mi<2;mi++){
        int r0 = m0 + wm*32 + mi*16 + q;
        float s0 = As[(size_t)r0*KS + kc] * sw;
        float s1 = As[(size_t)(r0+8)*KS + kc] * sw;
#pragma unroll
        for(int ni=0;ni<8;ni++){
            acc[mi][ni][0] = fmaf(part[mi][ni][0], s0, acc[mi][ni][0]);
            acc[mi][ni][1] = fmaf(part[mi][ni][1], s0, acc[mi][ni][1]);
            acc[mi][ni][2] = fmaf(part[mi][ni][2], s1, acc[mi][ni][2]);
            acc[mi][ni][3] = fmaf(part[mi][ni][3], s1, acc[mi][ni][3]);
        }
    }
}

// ---- fused gate+up GEMM + SwiGLU + hidden quant (permuted fp8 out) ----
__global__ void __launch_bounds__(256, 1)
k_gemm_gu(const uint8_t* __restrict__ Aq, const float* __restrict__ As,
          const uint8_t* __restrict__ Wg, const float* __restrict__ Wsg,
          const uint8_t* __restrict__ Wu, const float* __restrict__ Wsu,
          uint8_t* __restrict__ hq, float* __restrict__ hs){
    extern __shared__ uint8_t sm8[];
    const int K = H_DIM, KS = KB_H, NK = KB_H;
    const int tid = threadIdx.x, wid = tid>>5, lane = tid&31;
    const int q = lane>>2, r = lane&3;
    const int wm = wid&3, wn = wid>>2;
    const int m0 = blockIdx.x<<7, n0 = blockIdx.y<<7;
    const float* wsgr = Wsg + (size_t)blockIdx.y*KS;
    const float* wsur = Wsu + (size_t)blockIdx.y*KS;

    uint8_t* sA  = sm8;
    uint8_t* sBg = sm8 + 2*BUF;
    uint8_t* sBu = sm8 + 4*BUF;

    float accG[2][8][4], accU[2][8][4];
#pragma unroll
    for(int a=0;a<2;a++)
#pragma unroll
        for(int b=0;b<8;b++)
#pragma unroll
            for(int c=0;c<4;c++){ accG[a][b][c]=0.f; accU[a][b][c]=0.f; }

    auto fill = [&](int kc, int buf){
#pragma unroll
        for(int j=0;j<12;j++){
            int idx = tid + j*256;
            int mat = idx >> 10, rem = idx & 1023;
            int row = rem >> 3, u = rem & 7;
            uint8_t* base = (mat==0) ? sA : (mat==1) ? sBg : sBu;
            const uint8_t* g = (mat==0) ? Aq + (size_t)(m0+row)*K
                             : (mat==1) ? Wg + (size_t)(n0+row)*K
                                        : Wu + (size_t)(n0+row)*K;
            cpasync16(base + buf*BUF + row*SMB + u*16, g + kc*128 + u*16);
        }
        asm volatile("cp.async.commit_group;\n");
    };

    fill(0, 0);
    for(int kc = 0; kc < NK; kc++){
        int buf = kc & 1;
        asm volatile("cp.async.wait_group 0;\n");
        __syncthreads();
        if(kc + 1 < NK) fill(kc+1, buf^1);

        const uint8_t* bA  = sA  + buf*BUF;
        const uint8_t* bBg = sBg + buf*BUF;
        const uint8_t* bBu = sBu + buf*BUF;

        float part[2][8][4];
#pragma unroll
        for(int a=0;a<2;a++)
#pragma unroll
            for(int b=0;b<8;b++)
#pragma unroll
                for(int c=0;c<4;c++) part[a][b][c]=0.f;
        chunk_mma(bA, bBg, wm, wn, q, r, part);
        fold(part, accG, As, wsgr, kc, KS, m0, wm, q);
#pragma unroll
        for(int a=0;a<2;a++)
#pragma unroll
            for(int b=0;b<8;b++)
#pragma unroll
                for(int c=0;c<4;c++) part[a][b][c]=0.f;
        chunk_mma(bA, bBu, wm, wn, q, r, part);
        fold(part, accU, As, wsur, kc, KS, m0, wm, q);
        __syncthreads();
    }

    // epilogue: h = silu(gate)*up; per-row amax over this 128-col tile;
    // quantize to fp8 bytes (permuted layout) + write hs
#pragma unroll
    for(int mi=0;mi<2;mi++)
#pragma unroll
        for(int ni=0;ni<8;ni++)
#pragma unroll
            for(int c=0;c<4;c++){
                float g = accG[mi][ni][c];
                accG[mi][ni][c] = g * sigmoid_precise(g) * accU[mi][ni][c];
            }
    float* red = (float*)sm8;   // [2][128]
#pragma unroll
    for(int mi=0;mi<2;mi++){
        float a0 = 0.f, a1 = 0.f;
#pragma unroll
        for(int ni=0;ni<8;ni++){
            a0 = fmaxf(a0, fmaxf(fabsf(accG[mi][ni][0]), fabsf(accG[mi][ni][1])));
            a1 = fmaxf(a1, fmaxf(fabsf(accG[mi][ni][2]), fabsf(accG[mi][ni][3])));
        }
        a0 = fmaxf(a0, __shfl_xor_sync(0xffffffffu, a0, 1));
        a0 = fmaxf(a0, __shfl_xor_sync(0xffffffffu, a0, 2));
        a1 = fmaxf(a1, __shfl_xor_sync(0xffffffffu, a1, 1));
        a1 = fmaxf(a1, __shfl_xor_sync(0xffffffffu, a1, 2));
        if(r == 0){
            int rl = wm*32 + mi*16 + q;
            red[wn*128 + rl] = a0;
            red[wn*128 + rl + 8] = a1;
        }
    }
    __syncthreads();
    const int gidx = blockIdx.y;
#pragma unroll
    for(int mi=0;mi<2;mi++){
        int rl0 = wm*32 + mi*16 + q;
        float am0 = fmaxf(red[rl0], red[128+rl0]);
        float am1 = fmaxf(red[rl0+8], red[128+rl0+8]);
        float s0 = fmaxf(__fdiv_rn(am0, 448.0f), 1e-12f);
        float s1 = fmaxf(__fdiv_rn(am1, 448.0f), 1e-12f);
        if(wn == 0 && r == 0){
            hs[(size_t)(m0+rl0)*KB_I + gidx] = s0;
            hs[(size_t)(m0+rl0+8)*KB_I + gidx] = s1;
        }
#pragma unroll
        for(int ni=0;ni<8;ni+=2){
            // 32-bit permuted word: cols {c,c+1,c+8,c+9}, c = wn*64+ni*8+2r
            size_t coff = (size_t)n0 + wn*64 + (ni>>1)*16 + r*4;
            uint32_t w0 = fq8(accG[mi][ni][0],s0)   | (fq8(accG[mi][ni][1],s0)<<8)
                        | (fq8(accG[mi][ni+1][0],s0)<<16) | (fq8(accG[mi][ni+1][1],s0)<<24);
            uint32_t w1 = fq8(accG[mi][ni][2],s1)   | (fq8(accG[mi][ni][3],s1)<<8)
                        | (fq8(accG[mi][ni+1][2],s1)<<16) | (fq8(accG[mi][ni+1][3],s1)<<24);
            *(uint32_t*)(hq + (size_t)(m0+rl0)*I_DIM + coff)   = w0;
            *(uint32_t*)(hq + (size_t)(m0+rl0+8)*I_DIM + coff) = w1;
        }
    }
}

// ---- down GEMM: out = (hq*hs) @ (Wd*Wsd)^T ----
__global__ void __launch_bounds__(256, 1)
k_gemm_dn(const uint8_t* __restrict__ Aq, const float* __restrict__ As,
          const uint8_t* __restrict__ W,  const float* __restrict__ Ws,
          float* __restrict__ out){
    extern __shared__ uint8_t sm8[];
    const int K = I_DIM, KS = KB_I, NK = KB_I, N = H_DIM;
    const int tid = threadIdx.x, wid = tid>>5, lane = tid&31;
    const int q = lane>>2, r = lane&3;
    const int wm = wid&3, wn = wid>>2;
    const int m0 = blockIdx.x<<7, n0 = blockIdx.y<<7;
    const float* wsr = Ws + (size_t)blockIdx.y*KS;

    uint8_t* sA = sm8;
    uint8_t* sB = sm8 + 2*BUF;

    float acc[2][8][4];
#pragma unroll
    for(int a=0;a<2;a++)
#pragma unroll
        for(int b=0;b<8;b++)
#pragma unroll
            for(int c=0;c<4;c++) acc[a][b][c]=0.f;

    auto fill = [&](int kc, int buf){
#pragma unroll
        for(int j=0;j<8;j++){
            int idx = tid + j*256;
            int mat = idx >> 10, rem = idx & 1023;
            int row = rem >> 3, u = rem & 7;
            uint8_t* base = mat ? sB : sA;
            const uint8_t* g = mat ? W + (size_t)(n0+row)*K : Aq + (size_t)(m0+row)*K;
            cpasync16(base + buf*BUF + row*SMB + u*16, g + kc*128 + u*16);
        }
        asm volatile("cp.async.commit_group;\n");
    };

    fill(0, 0);
    for(int kc = 0; kc < NK; kc++){
        int buf = kc & 1;
        asm volatile("cp.async.wait_group 0;\n");
        __syncthreads();
        if(kc + 1 < NK) fill(kc+1, buf^1);
        const uint8_t* bA = sA + buf*BUF;
        const uint8_t* bB = sB + buf*BUF;
        float part[2][8][4];
#pragma unroll
        for(int a=0;a<2;a++)
#pragma unroll
            for(int b=0;b<8;b++)
#pragma unroll
                for(int c=0;c<4;c++) part[a][b][c]=0.f;
        chunk_mma(bA, bB, wm, wn, q, r, part);
        fold(part, acc, As, wsr, kc, KS, m0, wm, q);
        __syncthreads();
    }
#pragma unroll
    for(int mi=0;mi<2;mi++){
        int r0 = m0 + wm*32 + mi*16 + q;
#pragma unroll
        for(int ni=0;ni<8;ni++){
            int c = n0 + wn*64 + ni*8 + r*2;
            *(float2*)(out + (size_t)r0*N + c)     = make_float2(acc[mi][ni][0], acc[mi][ni][1]);
            *(float2*)(out + (size_t)(r0+8)*N + c) = make_float2(acc[mi][ni][2], acc[mi][ni][3]);
        }
    }
}

extern "C" void kernel_launch(void* const* d_in, const int* in_sizes, int n_in,
                              void* d_out, int out_size){
    const float* x = (const float*)d_in[0];
    const void*  wg = d_in[1]; const float* wgs = (const float*)d_in[2];
    const void*  wu = d_in[3]; const float* wus = (const float*)d_in[4];
    const void*  wd = d_in[5]; const float* wds = (const float*)d_in[6];
    float* out = (float*)d_out;

    uint8_t *p_wg, *p_wu, *p_wd, *p_xq, *p_hq;
    float *p_xs, *p_hs;
    cudaGetSymbolAddress((void**)&p_wg, g_wg);
    cudaGetSymbolAddress((void**)&p_wu, g_wu);
    cudaGetSymbolAddress((void**)&p_wd, g_wd);
    cudaGetSymbolAddress((void**)&p_xq, g_xq);
    cudaGetSymbolAddress((void**)&p_xs, g_xs);
    cudaGetSymbolAddress((void**)&p_hq, g_hq);
    cudaGetSymbolAddress((void**)&p_hs, g_hs);

    static bool attr_set = false;
    const int smem_gu = 6*BUF;  // 110592
    const int smem_dn = 4*BUF;  // 73728
    if(!attr_set){
        cudaFuncSetAttribute(k_gemm_gu, cudaFuncAttributeMaxDynamicSharedMemorySize, smem_gu);
        cudaFuncSetAttribute(k_gemm_dn, cudaFuncAttributeMaxDynamicSharedMemorySize, smem_dn);
        attr_set = true;
    }

    k_detect<<<1, 256>>>(wg);
    k_convert<<<2048, 256>>>(wg, p_wg, (size_t)I_DIM*H_DIM);
    k_convert<<<2048, 256>>>(wu, p_wu, (size_t)I_DIM*H_DIM);
    k_convert<<<2048, 256>>>(wd, p_wd, (size_t)H_DIM*I_DIM);

    k_quant_x<<<(M_DIM*KB_H)/8, 256>>>(x, p_xq, p_xs);

    dim3 gGU(M_DIM/128, I_DIM/128);
    k_gemm_gu<<<gGU, 256, smem_gu>>>(p_xq, p_xs, p_wg, wgs, p_wu, wus, p_hq, p_hs);

    dim3 gD(M_DIM/128, H_DIM/128);
    k_gemm_dn<<<gD, 256, smem_dn>>>(p_hq, p_hs, p_wd, wds, out);
}